// round 11
// baseline (speedup 1.0000x reference)
#include <cuda_runtime.h>
#include <cuda_fp16.h>
#include <cstdint>

#define BB 8
#define TT 256
#define UU 64
#define ENC_DIM 512
#define PRED_DIM 640
#define JDIM 512
#define VOCAB 1024
#define MROWS (BB * TT * UU)   // 131072

// ---------------------------------------------------------------------------
// Device scratch
// ---------------------------------------------------------------------------
__device__ float g_enc_p[BB * TT * JDIM];            // 4 MB
__device__ float g_pred_p[BB * UU * JDIM];           // 1 MB
__device__ __half g_wt[VOCAB * JDIM];                // 1 MB  (W^T fp16)

// ---------------------------------------------------------------------------
// Helpers
// ---------------------------------------------------------------------------
__device__ __forceinline__ uint32_t smem_u32(const void* p) {
    uint32_t a;
    asm("{ .reg .u64 t; cvta.to.shared.u64 t, %1; cvt.u32.u64 %0, t; }" : "=r"(a) : "l"(p));
    return a;
}
#define CP16(dst, src) \
    asm volatile("cp.async.cg.shared.global [%0], [%1], 16;" :: "r"((uint32_t)(dst)), "l"(src) : "memory")
#define CP_COMMIT() asm volatile("cp.async.commit_group;" ::: "memory")

#define LDSM4(r, addr) \
    asm volatile("ldmatrix.sync.aligned.m8n8.x4.shared.b16 {%0,%1,%2,%3}, [%4];" \
                 : "=r"((r)[0]), "=r"((r)[1]), "=r"((r)[2]), "=r"((r)[3]) : "r"(addr))

#define MMA16816(acc, a, b0, b1) \
    asm volatile("mma.sync.aligned.m16n8k16.row.col.f32.f16.f16.f32 " \
                 "{%0,%1,%2,%3},{%4,%5,%6,%7},{%8,%9},{%0,%1,%2,%3};" \
                 : "+f"((acc)[0]), "+f"((acc)[1]), "+f"((acc)[2]), "+f"((acc)[3]) \
                 : "r"((a)[0]), "r"((a)[1]), "r"((a)[2]), "r"((a)[3]), "r"(b0), "r"(b1))

#define STS128(addr, r0, r1, r2, r3) \
    asm volatile("st.shared.v4.b32 [%0], {%1,%2,%3,%4};" \
                 :: "r"(addr), "r"(r0), "r"(r1), "r"(r2), "r"(r3))

// HW tanh (MUFU.TANH): ~2^-11 accuracy, matches fp16 quantization scale
__device__ __forceinline__ float tanh_hw(float x) {
    float y;
    asm("tanh.approx.f32 %0, %1;" : "=f"(y) : "f"(x));
    return y;
}
__device__ __forceinline__ uint32_t pack2h(__half a, __half b) {
    return (uint32_t)__half_as_ushort(a) | ((uint32_t)__half_as_ushort(b) << 16);
}

// ---------------------------------------------------------------------------
// Projection GEMM (fp32 SIMT): C[M, 512] = A[M, K] @ W[K, 512] + bias
// BM=64, BN=64, 256 threads, 4x4 microtile
// ---------------------------------------------------------------------------
template <int K, int WHICH>
__global__ __launch_bounds__(256) void proj_kernel(
    const float* __restrict__ A, const float* __restrict__ W, const float* __restrict__ bias)
{
    __shared__ float As[16][68];
    __shared__ float Bs[16][68];
    float* __restrict__ C = (WHICH == 0) ? g_enc_p : g_pred_p;
    const int N = JDIM;
    const int tid = threadIdx.x;
    const int ty = tid >> 4, tx = tid & 15;
    const int m0 = blockIdx.y * 64, n0 = blockIdx.x * 64;
    const int lm = tid >> 2, lk = (tid & 3) << 2;
    const int bk = tid >> 4, bn = (tid & 15) << 2;

    float acc[4][4];
#pragma unroll
    for (int i = 0; i < 4; i++)
#pragma unroll
        for (int j = 0; j < 4; j++) acc[i][j] = 0.0f;

    for (int k0 = 0; k0 < K; k0 += 16) {
        float4 a4 = *(const float4*)&A[(m0 + lm) * K + k0 + lk];
        As[lk + 0][lm] = a4.x; As[lk + 1][lm] = a4.y;
        As[lk + 2][lm] = a4.z; As[lk + 3][lm] = a4.w;
        *(float4*)&Bs[bk][bn] = *(const float4*)&W[(k0 + bk) * N + n0 + bn];
        __syncthreads();
#pragma unroll
        for (int k = 0; k < 16; k++) {
            float4 av = *(const float4*)&As[k][ty << 2];
            float4 bv = *(const float4*)&Bs[k][tx << 2];
            float a[4] = {av.x, av.y, av.z, av.w};
            float b[4] = {bv.x, bv.y, bv.z, bv.w};
#pragma unroll
            for (int i = 0; i < 4; i++)
#pragma unroll
                for (int j = 0; j < 4; j++) acc[i][j] = fmaf(a[i], b[j], acc[i][j]);
        }
        __syncthreads();
    }
#pragma unroll
    for (int j = 0; j < 4; j++) {
        float bj = bias[n0 + (tx << 2) + j];
#pragma unroll
        for (int i = 0; i < 4; i++)
            C[(m0 + (ty << 2) + i) * N + n0 + (tx << 2) + j] = acc[i][j] + bj;
    }
}

// ---------------------------------------------------------------------------
// prep_W: Wt[v,k] = fp16(W_joint[k,v])
// ---------------------------------------------------------------------------
__global__ __launch_bounds__(256) void prep_w_kernel(const float* __restrict__ W) {
    int gid = blockIdx.x * 256 + threadIdx.x;       // 0 .. 524287
    int v = gid >> 9, k = gid & 511;
    g_wt[gid] = __float2half_rn(W[k * VOCAB + v]);
}

// ---------------------------------------------------------------------------
// Fused joint GEMM: C = tanh(enc_p (+) pred_p)_fp16 @ Wt_fp16^T + bias
// BM=128, BN=256, BK=64, 256 threads (8 warps 2x4), warp tile 64x64.
// B: 3-stage cp.async pipeline. A: computed in-kernel (LDG fp32 from
// L2-resident enc_p/pred_p + MUFU tanh + STS fp16), double-buffered.
// LDGs for A(s+1) issue before the MMA wall of stage s; tanh+STS after.
// ---------------------------------------------------------------------------
#define BM 128
#define BN 256
#define BK 64
#define NSTG 8                          // 512 / 64
#define NPIPE 3                         // B stages
#define ASTRIDE 144                     // 64 fp16 = 128B data, padded to 144B
#define A_PLANE (BM * ASTRIDE)          // 18432
#define B_PLANE (BN * ASTRIDE)          // 36864
#define OFF_B 0
#define OFF_A (NPIPE * B_PLANE)                         // 110592
#define JOINT_SMEM (NPIPE * B_PLANE + 2 * A_PLANE + 1024)  // 148480

__device__ __forceinline__ void load_b_stage(uint32_t sbase, int k0, int n0, int tid) {
#pragma unroll
    for (int it = 0; it < 8; it++) {
        int c = tid + it * 256;            // 0..2047
        int row = c >> 3, cq = c & 7;
        CP16(sbase + row * ASTRIDE + cq * 16,
             g_wt + (size_t)(n0 + row) * JDIM + k0 + cq * 8);
    }
}

// Load the fp32 inputs for this thread's 32 A elements of stage k0.
__device__ __forceinline__ void load_a_inputs(float4* e, float4* p,
                                              int k0, int bt0, int b, int tid) {
    const int r = tid >> 1, h = tid & 1;
    const int bt = bt0 + (r >> 6), u = r & 63;
    const float4* ep = (const float4*)(g_enc_p + (size_t)bt * JDIM + k0 + h * 32);
    const float4* pp = (const float4*)(g_pred_p + ((size_t)(b * UU + u)) * JDIM + k0 + h * 32);
#pragma unroll
    for (int i = 0; i < 8; i++) e[i] = ep[i];
#pragma unroll
    for (int i = 0; i < 8; i++) p[i] = pp[i];
}

// tanh + pack + store this thread's 32 A elements into smem buffer abase.
__device__ __forceinline__ void finish_a(uint32_t abase, const float4* e, const float4* p, int tid) {
    const int r = tid >> 1, h = tid & 1;
    uint32_t o[16];
#pragma unroll
    for (int i = 0; i < 8; i++) {
        __half a0 = __float2half_rn(tanh_hw(e[i].x + p[i].x));
        __half a1 = __float2half_rn(tanh_hw(e[i].y + p[i].y));
        __half a2 = __float2half_rn(tanh_hw(e[i].z + p[i].z));
        __half a3 = __float2half_rn(tanh_hw(e[i].w + p[i].w));
        o[i * 2 + 0] = pack2h(a0, a1);
        o[i * 2 + 1] = pack2h(a2, a3);
    }
    const uint32_t dst = abase + r * ASTRIDE + h * 64;
#pragma unroll
    for (int q = 0; q < 4; q++)
        STS128(dst + q * 16, o[q * 4 + 0], o[q * 4 + 1], o[q * 4 + 2], o[q * 4 + 3]);
}

__global__ __launch_bounds__(256, 1) void joint_kernel(
    const float* __restrict__ bias, float* __restrict__ out)
{
    extern __shared__ char dsm[];
    const uint32_t sb = smem_u32(dsm);
    float* sbias = (float*)(dsm + NPIPE * B_PLANE + 2 * A_PLANE);

    const int tid = threadIdx.x;
    const int l   = tid & 31;
    const int w   = tid >> 5;
    const int mw  = w & 1;        // 0..1  -> 64-row slab
    const int nw  = w >> 1;       // 0..3  -> 64-col slab
    const int bid = blockIdx.x;
    const int n0  = (bid & 3) * BN;      // n-major within m
    const int m0  = (bid >> 2) * BM;
    const int bt0 = m0 >> 6;
    const int b   = bt0 >> 8;

    sbias[tid] = bias[n0 + tid];

    // B prologue: stages 0,1
    load_b_stage(sb + OFF_B + 0 * B_PLANE, 0 * BK, n0, tid); CP_COMMIT();
    load_b_stage(sb + OFF_B + 1 * B_PLANE, 1 * BK, n0, tid); CP_COMMIT();

    // A prologue: compute stage 0 into abuf 0
    {
        float4 e[8], p[8];
        load_a_inputs(e, p, 0, bt0, b, tid);
        finish_a(sb + OFF_A + 0 * A_PLANE, e, p, tid);
    }

    float acc[4][8][4];
#pragma unroll
    for (int i = 0; i < 4; i++)
#pragma unroll
        for (int j = 0; j < 8; j++)
#pragma unroll
            for (int q = 0; q < 4; q++) acc[i][j][q] = 0.0f;

    const uint32_t a_off = (uint32_t)((mw * 64 + (l & 15)) * ASTRIDE + (l >> 4) * 16);
    const uint32_t b_off = (uint32_t)((nw * 64 + ((l >> 4) << 3) + (l & 7)) * ASTRIDE
                                      + ((l >> 3) & 1) * 16);

    for (int s = 0; s < NSTG; s++) {
        // B(s) resident; A(s) STS visible
        asm volatile("cp.async.wait_group 1;" ::: "memory");
        __syncthreads();

        const uint32_t stgB = sb + OFF_B + (s % NPIPE) * B_PLANE;
        const uint32_t stgA = sb + OFF_A + (s & 1) * A_PLANE;

        // issue LDGs for A(s+1) early — consumed after the MMA wall
        float4 e[8], p[8];
        if (s + 1 < NSTG) load_a_inputs(e, p, (s + 1) * BK, bt0, b, tid);

        uint32_t aa[2][4][4], bb[2][4][4];

        // ---- kk-pair 0 (kk = 0,1) ----
#pragma unroll
        for (int kk = 0; kk < 2; kk++) {
#pragma unroll
            for (int mf = 0; mf < 4; mf++)
                LDSM4(aa[kk][mf], stgA + a_off + kk * 32 + mf * 16 * ASTRIDE);
#pragma unroll
            for (int np = 0; np < 4; np++)
                LDSM4(bb[kk][np], stgB + b_off + kk * 32 + np * 16 * ASTRIDE);
        }
        // prefetch B(s+2) in the shadow (uniform commit)
        if (s + 2 < NSTG)
            load_b_stage(sb + OFF_B + ((s + 2) % NPIPE) * B_PLANE, (s + 2) * BK, n0, tid);
        CP_COMMIT();
#pragma unroll
        for (int kk = 0; kk < 2; kk++)
#pragma unroll
            for (int mf = 0; mf < 4; mf++)
#pragma unroll
                for (int np = 0; np < 4; np++) {
                    MMA16816(acc[mf][np * 2 + 0], aa[kk][mf], bb[kk][np][0], bb[kk][np][1]);
                    MMA16816(acc[mf][np * 2 + 1], aa[kk][mf], bb[kk][np][2], bb[kk][np][3]);
                }

        // ---- kk-pair 1 (kk = 2,3), registers reused ----
#pragma unroll
        for (int kk = 0; kk < 2; kk++) {
#pragma unroll
            for (int mf = 0; mf < 4; mf++)
                LDSM4(aa[kk][mf], stgA + a_off + 64 + kk * 32 + mf * 16 * ASTRIDE);
#pragma unroll
            for (int np = 0; np < 4; np++)
                LDSM4(bb[kk][np], stgB + b_off + 64 + kk * 32 + np * 16 * ASTRIDE);
        }
#pragma unroll
        for (int kk = 0; kk < 2; kk++)
#pragma unroll
            for (int mf = 0; mf < 4; mf++)
#pragma unroll
                for (int np = 0; np < 4; np++) {
                    MMA16816(acc[mf][np * 2 + 0], aa[kk][mf], bb[kk][np][0], bb[kk][np][1]);
                    MMA16816(acc[mf][np * 2 + 1], aa[kk][mf], bb[kk][np][2], bb[kk][np][3]);
                }

        // tanh + pack + store A(s+1) into the other A buffer (LDGs have had
        // the whole MMA wall to land)
        if (s + 1 < NSTG)
            finish_a(sb + OFF_A + ((s + 1) & 1) * A_PLANE, e, p, tid);
    }

    // epilogue: add bias, direct stores
#pragma unroll
    for (int mf = 0; mf < 4; mf++) {
        const int r0 = m0 + mw * 64 + mf * 16 + (l >> 2);
#pragma unroll
        for (int nf = 0; nf < 8; nf++) {
            const int c  = n0 + nw * 64 + nf * 8 + ((l & 3) << 1);
            const float2 b2 = *(const float2*)&sbias[c - n0];
            float2 o0, o1;
            o0.x = acc[mf][nf][0] + b2.x;
            o0.y = acc[mf][nf][1] + b2.y;
            o1.x = acc[mf][nf][2] + b2.x;
            o1.y = acc[mf][nf][3] + b2.y;
            *(float2*)&out[(size_t)r0 * VOCAB + c]       = o0;
            *(float2*)&out[(size_t)(r0 + 8) * VOCAB + c] = o1;
        }
    }
}

// ---------------------------------------------------------------------------
extern "C" void kernel_launch(void* const* d_in, const int* in_sizes, int n_in,
                              void* d_out, int out_size)
{
    const float* enc_out  = (const float*)d_in[0];
    const float* pred_out = (const float*)d_in[1];
    const float* W_enc    = (const float*)d_in[2];
    const float* b_enc    = (const float*)d_in[3];
    const float* W_pred   = (const float*)d_in[4];
    const float* b_pred   = (const float*)d_in[5];
    const float* W_joint  = (const float*)d_in[6];
    const float* b_joint  = (const float*)d_in[7];
    float* out = (float*)d_out;

    static bool attr_done = false;
    if (!attr_done) {
        cudaFuncSetAttribute(joint_kernel, cudaFuncAttributeMaxDynamicSharedMemorySize, JOINT_SMEM);
        attr_done = true;
    }

    {
        dim3 grid(JDIM / 64, (BB * TT) / 64);   // 256 blocks
        proj_kernel<ENC_DIM, 0><<<grid, 256>>>(enc_out, W_enc, b_enc);
    }
    {
        dim3 grid(JDIM / 64, (BB * UU) / 64);   // 64 blocks
        proj_kernel<PRED_DIM, 1><<<grid, 256>>>(pred_out, W_pred, b_pred);
    }
    prep_w_kernel<<<(VOCAB * JDIM) / 256, 256>>>(W_joint);
    // fused joint: 1024 m-tiles x 4 n-tiles, n-major within m
    joint_kernel<<<(MROWS / BM) * (VOCAB / BN), 256, JOINT_SMEM>>>(b_joint, out);
}

// round 12
// speedup vs baseline: 1.0914x; 1.0914x over previous
#include <cuda_runtime.h>
#include <cuda_fp16.h>
#include <cstdint>

#define BB 8
#define TT 256
#define UU 64
#define ENC_DIM 512
#define PRED_DIM 640
#define JDIM 512
#define VOCAB 1024
#define MROWS (BB * TT * UU)   // 131072

// ---------------------------------------------------------------------------
// Device scratch
// ---------------------------------------------------------------------------
__device__ float g_enc_p[BB * TT * JDIM];            // 4 MB
__device__ float g_pred_p[BB * UU * JDIM];           // 1 MB
__device__ __half g_wt[VOCAB * JDIM];                // 1 MB  (W^T fp16)

// ---------------------------------------------------------------------------
// Helpers
// ---------------------------------------------------------------------------
__device__ __forceinline__ uint32_t smem_u32(const void* p) {
    uint32_t a;
    asm("{ .reg .u64 t; cvta.to.shared.u64 t, %1; cvt.u32.u64 %0, t; }" : "=r"(a) : "l"(p));
    return a;
}
#define CP16(dst, src) \
    asm volatile("cp.async.cg.shared.global [%0], [%1], 16;" :: "r"((uint32_t)(dst)), "l"(src) : "memory")
#define CP_COMMIT() asm volatile("cp.async.commit_group;" ::: "memory")

#define LDSM4(r, addr) \
    asm volatile("ldmatrix.sync.aligned.m8n8.x4.shared.b16 {%0,%1,%2,%3}, [%4];" \
                 : "=r"((r)[0]), "=r"((r)[1]), "=r"((r)[2]), "=r"((r)[3]) : "r"(addr))

#define MMA16816(acc, a, b0, b1) \
    asm volatile("mma.sync.aligned.m16n8k16.row.col.f32.f16.f16.f32 " \
                 "{%0,%1,%2,%3},{%4,%5,%6,%7},{%8,%9},{%0,%1,%2,%3};" \
                 : "+f"((acc)[0]), "+f"((acc)[1]), "+f"((acc)[2]), "+f"((acc)[3]) \
                 : "r"((a)[0]), "r"((a)[1]), "r"((a)[2]), "r"((a)[3]), "r"(b0), "r"(b1))

#define STS128(addr, r0, r1, r2, r3) \
    asm volatile("st.shared.v4.b32 [%0], {%1,%2,%3,%4};" \
                 :: "r"(addr), "r"(r0), "r"(r1), "r"(r2), "r"(r3))

// HW tanh (MUFU.TANH): ~2^-11 accuracy, matches fp16 quantization scale
__device__ __forceinline__ float tanh_hw(float x) {
    float y;
    asm("tanh.approx.f32 %0, %1;" : "=f"(y) : "f"(x));
    return y;
}
__device__ __forceinline__ uint32_t pack2h(__half a, __half b) {
    return (uint32_t)__half_as_ushort(a) | ((uint32_t)__half_as_ushort(b) << 16);
}

// ---------------------------------------------------------------------------
// Projection GEMM (fp32 SIMT): C[M, 512] = A[M, K] @ W[K, 512] + bias
// BM=64, BN=64, 256 threads, 4x4 microtile
// ---------------------------------------------------------------------------
template <int K, int WHICH>
__global__ __launch_bounds__(256) void proj_kernel(
    const float* __restrict__ A, const float* __restrict__ W, const float* __restrict__ bias)
{
    __shared__ float As[16][68];
    __shared__ float Bs[16][68];
    float* __restrict__ C = (WHICH == 0) ? g_enc_p : g_pred_p;
    const int N = JDIM;
    const int tid = threadIdx.x;
    const int ty = tid >> 4, tx = tid & 15;
    const int m0 = blockIdx.y * 64, n0 = blockIdx.x * 64;
    const int lm = tid >> 2, lk = (tid & 3) << 2;
    const int bk = tid >> 4, bn = (tid & 15) << 2;

    float acc[4][4];
#pragma unroll
    for (int i = 0; i < 4; i++)
#pragma unroll
        for (int j = 0; j < 4; j++) acc[i][j] = 0.0f;

    for (int k0 = 0; k0 < K; k0 += 16) {
        float4 a4 = *(const float4*)&A[(m0 + lm) * K + k0 + lk];
        As[lk + 0][lm] = a4.x; As[lk + 1][lm] = a4.y;
        As[lk + 2][lm] = a4.z; As[lk + 3][lm] = a4.w;
        *(float4*)&Bs[bk][bn] = *(const float4*)&W[(k0 + bk) * N + n0 + bn];
        __syncthreads();
#pragma unroll
        for (int k = 0; k < 16; k++) {
            float4 av = *(const float4*)&As[k][ty << 2];
            float4 bv = *(const float4*)&Bs[k][tx << 2];
            float a[4] = {av.x, av.y, av.z, av.w};
            float b[4] = {bv.x, bv.y, bv.z, bv.w};
#pragma unroll
            for (int i = 0; i < 4; i++)
#pragma unroll
                for (int j = 0; j < 4; j++) acc[i][j] = fmaf(a[i], b[j], acc[i][j]);
        }
        __syncthreads();
    }
#pragma unroll
    for (int j = 0; j < 4; j++) {
        float bj = bias[n0 + (tx << 2) + j];
#pragma unroll
        for (int i = 0; i < 4; i++)
            C[(m0 + (ty << 2) + i) * N + n0 + (tx << 2) + j] = acc[i][j] + bj;
    }
}

// ---------------------------------------------------------------------------
// prep_W: Wt[v,k] = fp16(W_joint[k,v])
// ---------------------------------------------------------------------------
__global__ __launch_bounds__(256) void prep_w_kernel(const float* __restrict__ W) {
    int gid = blockIdx.x * 256 + threadIdx.x;       // 0 .. 524287
    int v = gid >> 9, k = gid & 511;
    g_wt[gid] = __float2half_rn(W[k * VOCAB + v]);
}

// ---------------------------------------------------------------------------
// Fused joint GEMM: C = tanh(enc_p (+) pred_p)_fp16 @ Wt_fp16^T + bias
// BM=128, BN=256, BK=64, 256 threads (8 warps 2x4), warp tile 64x64.
// B: 3-stage cp.async pipeline. A: computed in-kernel, double-buffered,
// in TWO 16-element chunks per stage so only 32 staging regs are ever live:
//   chunk LDG -> (MMA wall hides latency) -> tanh+pack+STS.
// ---------------------------------------------------------------------------
#define BM 128
#define BN 256
#define BK 64
#define NSTG 8                          // 512 / 64
#define NPIPE 3                         // B stages
#define ASTRIDE 144                     // 64 fp16 = 128B data, padded to 144B
#define A_PLANE (BM * ASTRIDE)          // 18432
#define B_PLANE (BN * ASTRIDE)          // 36864
#define OFF_B 0
#define OFF_A (NPIPE * B_PLANE)                            // 110592
#define JOINT_SMEM (NPIPE * B_PLANE + 2 * A_PLANE + 1024)  // 148480

__device__ __forceinline__ void load_b_stage(uint32_t sbase, int k0, int n0, int tid) {
#pragma unroll
    for (int it = 0; it < 8; it++) {
        int c = tid + it * 256;            // 0..2047
        int row = c >> 3, cq = c & 7;
        CP16(sbase + row * ASTRIDE + cq * 16,
             g_wt + (size_t)(n0 + row) * JDIM + k0 + cq * 8);
    }
}

// Load fp32 inputs for one 16-element chunk (4 float4 pairs = 32 regs).
__device__ __forceinline__ void load_a_chunk(float4* e, float4* p, int k0, int chunk,
                                             int bt0, int b, int tid) {
    const int r = tid >> 1, h = tid & 1;
    const int bt = bt0 + (r >> 6), u = r & 63;
    const int ko = k0 + h * 32 + chunk * 16;
    const float4* ep = (const float4*)(g_enc_p + (size_t)bt * JDIM + ko);
    const float4* pp = (const float4*)(g_pred_p + ((size_t)(b * UU + u)) * JDIM + ko);
#pragma unroll
    for (int i = 0; i < 4; i++) e[i] = ep[i];
#pragma unroll
    for (int i = 0; i < 4; i++) p[i] = pp[i];
}

// tanh + pack + STS one 16-element chunk (32 bytes) into buffer abase.
__device__ __forceinline__ void finish_a_chunk(uint32_t abase, const float4* e, const float4* p,
                                               int chunk, int tid) {
    const int r = tid >> 1, h = tid & 1;
    uint32_t o[8];
#pragma unroll
    for (int i = 0; i < 4; i++) {
        __half a0 = __float2half_rn(tanh_hw(e[i].x + p[i].x));
        __half a1 = __float2half_rn(tanh_hw(e[i].y + p[i].y));
        __half a2 = __float2half_rn(tanh_hw(e[i].z + p[i].z));
        __half a3 = __float2half_rn(tanh_hw(e[i].w + p[i].w));
        o[i * 2 + 0] = pack2h(a0, a1);
        o[i * 2 + 1] = pack2h(a2, a3);
    }
    const uint32_t dst = abase + r * ASTRIDE + h * 64 + chunk * 32;
    STS128(dst +  0, o[0], o[1], o[2], o[3]);
    STS128(dst + 16, o[4], o[5], o[6], o[7]);
}

__global__ __launch_bounds__(256, 1) void joint_kernel(
    const float* __restrict__ bias, float* __restrict__ out)
{
    extern __shared__ char dsm[];
    const uint32_t sb = smem_u32(dsm);
    float* sbias = (float*)(dsm + NPIPE * B_PLANE + 2 * A_PLANE);

    const int tid = threadIdx.x;
    const int l   = tid & 31;
    const int w   = tid >> 5;
    const int mw  = w & 1;        // 0..1  -> 64-row slab
    const int nw  = w >> 1;       // 0..3  -> 64-col slab
    const int bid = blockIdx.x;
    const int n0  = (bid & 3) * BN;      // n-major within m
    const int m0  = (bid >> 2) * BM;
    const int bt0 = m0 >> 6;
    const int b   = bt0 >> 8;

    sbias[tid] = bias[n0 + tid];

    // B prologue: stages 0,1
    load_b_stage(sb + OFF_B + 0 * B_PLANE, 0 * BK, n0, tid); CP_COMMIT();
    load_b_stage(sb + OFF_B + 1 * B_PLANE, 1 * BK, n0, tid); CP_COMMIT();

    // A prologue: compute stage 0 into abuf 0 (chunked; only 32 regs live)
    {
        float4 e[4], p[4];
        load_a_chunk(e, p, 0, 0, bt0, b, tid);
        finish_a_chunk(sb + OFF_A, e, p, 0, tid);
        load_a_chunk(e, p, 0, 1, bt0, b, tid);
        finish_a_chunk(sb + OFF_A, e, p, 1, tid);
    }

    float acc[4][8][4];
#pragma unroll
    for (int i = 0; i < 4; i++)
#pragma unroll
        for (int j = 0; j < 8; j++)
#pragma unroll
            for (int q = 0; q < 4; q++) acc[i][j][q] = 0.0f;

    const uint32_t a_off = (uint32_t)((mw * 64 + (l & 15)) * ASTRIDE + (l >> 4) * 16);
    const uint32_t b_off = (uint32_t)((nw * 64 + ((l >> 4) << 3) + (l & 7)) * ASTRIDE
                                      + ((l >> 3) & 1) * 16);

    for (int s = 0; s < NSTG; s++) {
        // B(s) resident; A(s) STS visible
        asm volatile("cp.async.wait_group 1;" ::: "memory");
        __syncthreads();

        const uint32_t stgB = sb + OFF_B + (s % NPIPE) * B_PLANE;
        const uint32_t stgA = sb + OFF_A + (s & 1) * A_PLANE;
        const uint32_t nxtA = sb + OFF_A + ((s + 1) & 1) * A_PLANE;
        const bool more = (s + 1 < NSTG);

        uint32_t aa[2][4][4], bb[2][4][4];
        float4 e[4], p[4];

        // ---- LDSM kk-pair 0 (kk = 0,1) ----
#pragma unroll
        for (int kk = 0; kk < 2; kk++) {
#pragma unroll
            for (int mf = 0; mf < 4; mf++)
                LDSM4(aa[kk][mf], stgA + a_off + kk * 32 + mf * 16 * ASTRIDE);
#pragma unroll
            for (int np = 0; np < 4; np++)
                LDSM4(bb[kk][np], stgB + b_off + kk * 32 + np * 16 * ASTRIDE);
        }
        // prefetch B(s+2) in the shadow (uniform commit)
        if (s + 2 < NSTG)
            load_b_stage(sb + OFF_B + ((s + 2) % NPIPE) * B_PLANE, (s + 2) * BK, n0, tid);
        CP_COMMIT();

        // A(s+1) chunk 0 LDGs — land under MMA wall 0
        if (more) load_a_chunk(e, p, (s + 1) * BK, 0, bt0, b, tid);

        // ---- MMA wall 0 ----
#pragma unroll
        for (int kk = 0; kk < 2; kk++)
#pragma unroll
            for (int mf = 0; mf < 4; mf++)
#pragma unroll
                for (int np = 0; np < 4; np++) {
                    MMA16816(acc[mf][np * 2 + 0], aa[kk][mf], bb[kk][np][0], bb[kk][np][1]);
                    MMA16816(acc[mf][np * 2 + 1], aa[kk][mf], bb[kk][np][2], bb[kk][np][3]);
                }

        if (more) finish_a_chunk(nxtA, e, p, 0, tid);

        // ---- LDSM kk-pair 1 (kk = 2,3), registers reused ----
#pragma unroll
        for (int kk = 0; kk < 2; kk++) {
#pragma unroll
            for (int mf = 0; mf < 4; mf++)
                LDSM4(aa[kk][mf], stgA + a_off + 64 + kk * 32 + mf * 16 * ASTRIDE);
#pragma unroll
            for (int np = 0; np < 4; np++)
                LDSM4(bb[kk][np], stgB + b_off + 64 + kk * 32 + np * 16 * ASTRIDE);
        }

        // A(s+1) chunk 1 LDGs — land under MMA wall 1
        if (more) load_a_chunk(e, p, (s + 1) * BK, 1, bt0, b, tid);

        // ---- MMA wall 1 ----
#pragma unroll
        for (int kk = 0; kk < 2; kk++)
#pragma unroll
            for (int mf = 0; mf < 4; mf++)
#pragma unroll
                for (int np = 0; np < 4; np++) {
                    MMA16816(acc[mf][np * 2 + 0], aa[kk][mf], bb[kk][np][0], bb[kk][np][1]);
                    MMA16816(acc[mf][np * 2 + 1], aa[kk][mf], bb[kk][np][2], bb[kk][np][3]);
                }

        if (more) finish_a_chunk(nxtA, e, p, 1, tid);
    }

    // epilogue: add bias, direct stores
#pragma unroll
    for (int mf = 0; mf < 4; mf++) {
        const int r0 = m0 + mw * 64 + mf * 16 + (l >> 2);
#pragma unroll
        for (int nf = 0; nf < 8; nf++) {
            const int c  = n0 + nw * 64 + nf * 8 + ((l & 3) << 1);
            const float2 b2 = *(const float2*)&sbias[c - n0];
            float2 o0, o1;
            o0.x = acc[mf][nf][0] + b2.x;
            o0.y = acc[mf][nf][1] + b2.y;
            o1.x = acc[mf][nf][2] + b2.x;
            o1.y = acc[mf][nf][3] + b2.y;
            *(float2*)&out[(size_t)r0 * VOCAB + c]       = o0;
            *(float2*)&out[(size_t)(r0 + 8) * VOCAB + c] = o1;
        }
    }
}

// ---------------------------------------------------------------------------
extern "C" void kernel_launch(void* const* d_in, const int* in_sizes, int n_in,
                              void* d_out, int out_size)
{
    const float* enc_out  = (const float*)d_in[0];
    const float* pred_out = (const float*)d_in[1];
    const float* W_enc    = (const float*)d_in[2];
    const float* b_enc    = (const float*)d_in[3];
    const float* W_pred   = (const float*)d_in[4];
    const float* b_pred   = (const float*)d_in[5];
    const float* W_joint  = (const float*)d_in[6];
    const float* b_joint  = (const float*)d_in[7];
    float* out = (float*)d_out;

    static bool attr_done = false;
    if (!attr_done) {
        cudaFuncSetAttribute(joint_kernel, cudaFuncAttributeMaxDynamicSharedMemorySize, JOINT_SMEM);
        attr_done = true;
    }

    {
        dim3 grid(JDIM / 64, (BB * TT) / 64);   // 256 blocks
        proj_kernel<ENC_DIM, 0><<<grid, 256>>>(enc_out, W_enc, b_enc);
    }
    {
        dim3 grid(JDIM / 64, (BB * UU) / 64);   // 64 blocks
        proj_kernel<PRED_DIM, 1><<<grid, 256>>>(pred_out, W_pred, b_pred);
    }
    prep_w_kernel<<<(VOCAB * JDIM) / 256, 256>>>(W_joint);
    // fused joint: 1024 m-tiles x 4 n-tiles, n-major within m
    joint_kernel<<<(MROWS / BM) * (VOCAB / BN), 256, JOINT_SMEM>>>(b_joint, out);
}